// round 13
// baseline (speedup 1.0000x reference)
#include <cuda_runtime.h>
#include <math.h>

#define NUM_INITS   64
#define BATCH_N     128
#define TOTAL_P     18378
#define OFF_W1      0
#define OFF_B1      400
#define OFF_W2      416
#define OFF_B2      13216
#define OFF_WD      13248
#define OFF_BD      18368

// a1 padded layout: [img][ci][row(12) x stride 20]
#define A1_RS   20
#define A1_CS   240
#define A1_IS   3840

#define WPAD    101          // 101 = 5 mod 32 -> conflict-free per-lane weight rows

typedef unsigned long long ull;

__device__ __forceinline__ ull fma2(ull a, ull b, ull c) {
    ull d;
    asm("fma.rn.f32x2 %0, %1, %2, %3;" : "=l"(d) : "l"(a), "l"(b), "l"(c));
    return d;
}
__device__ __forceinline__ ull pack2(float lo, float hi) {
    ull d; asm("mov.b64 %0, {%1, %2};" : "=l"(d) : "f"(lo), "f"(hi)); return d;
}
__device__ __forceinline__ void unpack2(ull v, float& lo, float& hi) {
    asm("mov.b64 {%0, %1}, %2;" : "=f"(lo), "=f"(hi) : "l"(v));
}

__global__ __launch_bounds__(256, 2)
void ensemble_lenet_kernel(const float* __restrict__ params,
                           const float* __restrict__ batch,
                           float* __restrict__ out)
{
    __shared__ float s_w1[400];
    __shared__ float s_b1[16];
    __shared__ float s_b2[32];
    __shared__ __align__(16) float s_a1[2 * A1_IS];   // also reduce scratch
    __shared__ __align__(16) float s_u[32 * WPAD];    // union: img / w2 chunk
    __shared__ __align__(16) float s_a2[2][512];      // transposed [pos16][c2]
    __shared__ float s_dot[2][16];

    const int blk   = blockIdx.x;
    const int init  = blk >> 6;
    const int npair = blk & 63;
    const int t     = threadIdx.x;
    const int img   = t >> 7;
    const int tl    = t & 127;

    const float* __restrict__ P = params + init * TOTAL_P;

    // ---------- stage 2 images + conv1 params ----------
    {
        const float* ib = batch + (npair * 2) * 784;
        for (int idx = t; idx < 1568; idx += 256) s_u[idx] = ib[idx];
        for (int idx = t; idx < 400;  idx += 256) s_w1[idx] = P[idx];
        if (t < 16) s_b1[t] = P[OFF_B1 + t];
        if (t < 32) s_b2[t] = P[OFF_B2 + t];
    }
    __syncthreads();

    // ---------- conv1 + relu + pool (packed f32x2) ----------
    {
        const int co = (tl >> 3) & 15;
        const int l8 = tl & 7;
        ull wp1[25];
        #pragma unroll
        for (int q = 0; q < 25; q++) {
            const float w = s_w1[co * 25 + q];
            wp1[q] = pack2(w, w);
        }
        const float b1 = s_b1[co];
        const ull bpair = pack2(b1, b1);
        const float* imgp = s_u + img * 784;
        float* a1p = s_a1 + img * A1_IS + co * A1_CS;

        #pragma unroll 2
        for (int k = 0; k < 18; k++) {
            const int idx = l8 + (k << 3);       // 0..143
            const int py = idx / 12;
            const int px = idx - py * 12;
            const int iy = py * 2, ix = px * 2;

            ull p0 = bpair, p1 = bpair;          // (a00,a01), (a10,a11)
            #pragma unroll
            for (int r = 0; r < 6; r++) {
                const float2* rp = (const float2*)(imgp + (iy + r) * 28 + ix);
                const float2 v0 = rp[0], v1 = rp[1], v2 = rp[2];
                ull pr[5];
                pr[0] = pack2(v0.x, v0.y);
                pr[1] = pack2(v0.y, v1.x);
                pr[2] = pack2(v1.x, v1.y);
                pr[3] = pack2(v1.y, v2.x);
                pr[4] = pack2(v2.x, v2.y);
                if (r < 5) {
                    #pragma unroll
                    for (int dx = 0; dx < 5; dx++)
                        p0 = fma2(pr[dx], wp1[r * 5 + dx], p0);
                }
                if (r >= 1) {
                    #pragma unroll
                    for (int dx = 0; dx < 5; dx++)
                        p1 = fma2(pr[dx], wp1[(r - 1) * 5 + dx], p1);
                }
            }
            float a00, a01, a10, a11;
            unpack2(p0, a00, a01);
            unpack2(p1, a10, a11);
            const float m = fmaxf(fmaxf(a00, a01), fmaxf(a10, a11));
            a1p[py * A1_RS + px] = fmaxf(m, 0.0f);
        }
    }
    __syncthreads();

    // ---------- conv2 (packed f32x2): lane = c2, broadcast activations ----------
    const int wimg   = tl >> 5;
    const int half   = wimg & 1;
    const int rowgrp = wimg >> 1;
    const int c2     = tl & 31;
    const int y0     = rowgrp * 4;

    ull accp[16];                     // [yl*4 + xp], pair covers x = 2xp, 2xp+1
    {
        const float b = (half == 0) ? s_b2[c2] : 0.0f;
        const ull bp = pack2(b, b);
        #pragma unroll
        for (int k = 0; k < 16; k++) accp[k] = bp;
    }

    for (int cb = 0; cb < 4; cb++) {
        for (int idx = t; idx < 3200; idx += 256) {
            const int c   = idx / 100;
            const int rem = idx - c * 100;
            s_u[c * WPAD + rem] = P[OFF_W2 + c * 400 + cb * 100 + rem];
        }
        __syncthreads();

        #pragma unroll
        for (int cc = 0; cc < 2; cc++) {
            const int ciL = half * 2 + cc;
            const float* ap = s_a1 + img * A1_IS + (cb * 4 + ciL) * A1_CS;

            ull wp[25];               // (w,w) pairs, lane-distinct LDS
            #pragma unroll
            for (int q = 0; q < 25; q++) {
                const float w = s_u[c2 * WPAD + ciL * 25 + q];
                wp[q] = pack2(w, w);
            }

            #pragma unroll
            for (int r = 0; r < 8; r++) {
                const float2* rp = (const float2*)(ap + (y0 + r) * A1_RS);
                float2 e[6];
                #pragma unroll
                for (int k = 0; k < 6; k++) e[k] = rp[k];
                ull pr[11];
                #pragma unroll
                for (int k = 0; k < 6; k++) pr[2 * k] = pack2(e[k].x, e[k].y);
                #pragma unroll
                for (int k = 0; k < 5; k++) pr[2 * k + 1] = pack2(e[k].y, e[k + 1].x);

                #pragma unroll
                for (int yl = 0; yl < 4; yl++) {
                    const int s = r - yl;
                    if (s >= 0 && s <= 4) {
                        #pragma unroll
                        for (int dx = 0; dx < 5; dx++) {
                            const ull w = wp[s * 5 + dx];
                            #pragma unroll
                            for (int xp = 0; xp < 4; xp++)
                                accp[yl * 4 + xp] = fma2(pr[2 * xp + dx], w, accp[yl * 4 + xp]);
                        }
                    }
                }
            }
        }
        __syncthreads();
    }

    // unpack accumulators
    float acc[32];
    #pragma unroll
    for (int k = 0; k < 16; k++) unpack2(accp[k], acc[2 * k], acc[2 * k + 1]);
    // NOTE: acc layout now [yl][x] with acc[yl*8 + x] == unpacked pairs in order:
    // accp[yl*4+xp] -> acc[(yl*4+xp)*2 + {0,1}] = out(x=2xp, 2xp+1)  => same as acc[yl*8+x].

    // ---------- cross-half reduction + pool ----------
    {
        float* scr = s_a1 + ((img * 2 + rowgrp) * 32) * 32 + c2;
        if (half == 1) {
            #pragma unroll
            for (int k = 0; k < 32; k++) scr[k * 32] = acc[k];
        }
        __syncthreads();
        if (half == 0) {
            #pragma unroll
            for (int k = 0; k < 32; k++) acc[k] += scr[k * 32];
            #pragma unroll
            for (int pyL = 0; pyL < 2; pyL++) {
                #pragma unroll
                for (int px = 0; px < 4; px++) {
                    const float m = fmaxf(
                        fmaxf(acc[(pyL*2)*8 + px*2],   acc[(pyL*2)*8 + px*2 + 1]),
                        fmaxf(acc[(pyL*2+1)*8 + px*2], acc[(pyL*2+1)*8 + px*2 + 1]));
                    s_a2[img][((rowgrp * 2 + pyL) * 4 + px) * 32 + c2] = fmaxf(m, 0.0f);
                }
            }
        }
    }
    __syncthreads();

    // ---------- dense 512 -> 10 (warp-uniform) ----------
    {
        const int o  = tl >> 3;
        const int oc = (o < 10) ? o : 9;
        const int l  = tl & 7;
        const float2* wr2 = (const float2*)(P + OFF_WD + oc * 512 + l * 64);
        const float* a2 = s_a2[img];
        float partial = 0.0f;
        #pragma unroll
        for (int i2 = 0; i2 < 32; i2++) {
            const float2 w = wr2[i2];
            const int f0 = l * 64 + i2 * 2;
            partial = fmaf(w.x, a2[((f0    ) & 15) * 32 + ((f0    ) >> 4)], partial);
            partial = fmaf(w.y, a2[((f0 + 1) & 15) * 32 + ((f0 + 1) >> 4)], partial);
        }
        #pragma unroll
        for (int off = 4; off; off >>= 1)
            partial += __shfl_down_sync(0xFFFFFFFFu, partial, off, 8);
        if (l == 0 && o < 10) s_dot[img][o] = partial + P[OFF_BD + o];
    }
    __syncthreads();

    // ---------- log_softmax, write out ----------
    if (t < 64) {
        const int im = t >> 5;
        const int lane = t & 31;
        const float v = (lane < 10) ? s_dot[im][lane] : -INFINITY;
        float mx = v;
        #pragma unroll
        for (int off = 16; off; off >>= 1)
            mx = fmaxf(mx, __shfl_xor_sync(0xFFFFFFFFu, mx, off));
        const float e = (lane < 10) ? __expf(v - mx) : 0.0f;
        float s = e;
        #pragma unroll
        for (int off = 16; off; off >>= 1)
            s += __shfl_xor_sync(0xFFFFFFFFu, s, off);
        if (lane < 10) {
            const int n = npair * 2 + im;
            out[(init * BATCH_N + n) * 10 + lane] = v - mx - __logf(s);
        }
    }
}

extern "C" void kernel_launch(void* const* d_in, const int* in_sizes, int n_in,
                              void* d_out, int out_size)
{
    const float* params = (const float*)d_in[0];
    const float* batch  = (const float*)d_in[1];
    if (n_in >= 2 && in_sizes[0] != NUM_INITS * TOTAL_P) {
        params = (const float*)d_in[1];
        batch  = (const float*)d_in[0];
    }
    float* out = (float*)d_out;
    ensemble_lenet_kernel<<<NUM_INITS * (BATCH_N / 2), 256>>>(params, batch, out);
}